// round 9
// baseline (speedup 1.0000x reference)
#include <cuda_runtime.h>
#include <math.h>

#define Nn   65536
#define Ee   524288
#define Bb   128
#define Hh   3
#define HCc  192
#define NH2  32
#define KEEP 256
#define CAP  48
#define FULLM 0xffffffffu

// ---------------- scratch (device globals; no runtime allocation) ----------
__device__ float  g_xp[Nn * HCc];       // 50 MB
__device__ float4 g_asrc4[Nn];          // [node]{a0,a1,a2,-}
__device__ float4 g_adst4[Nn];
__device__ float  g_A[6];               // [h][j] edge-attn linear map
__device__ int    g_cnt[Nn];
__device__ float4 g_bucket[Nn * CAP];   // 48 MB {src, e0, e1, -}
__device__ float  g_x1[Nn * HCc];       // 50 MB
__device__ float  g_q[Nn];              // dinv * xw
__device__ float  g_dinv[Nn];
__device__ float  g_score[Nn];
__device__ float  g_r[Bb * 2 * HCc];

// ---------------- init + prepA ---------------------------------------------
__global__ void k_init(const float* __restrict__ W_edge,
                       const float* __restrict__ att_edge) {
    int i = blockIdx.x * blockDim.x + threadIdx.x;
    if (i < Nn) g_cnt[i] = 0;
    if (i < 6) {
        int h = i >> 1, j = i & 1;
        float s = 0.f;
        for (int c = 0; c < 64; c++)
            s += W_edge[(h * 64 + c) * 2 + j] * att_edge[h * 64 + c];
        g_A[i] = s;
    }
}

// ---------------- fused: h = elu(x@W_lin.T+b); xp = h@W_src.T; a_src/a_dst --
__global__ void k_feat(const float* __restrict__ x,
                       const float* __restrict__ W_lin,
                       const float* __restrict__ b_lin,
                       const float* __restrict__ Wsrc,
                       const float* __restrict__ att_s,
                       const float* __restrict__ att_d) {
    extern __shared__ float smem[];
    float4* sx    = (float4*)smem;            // 64*32  f4 = 32 KB
    float4* sWl   = sx + 2048;                // 32*32  f4 = 16 KB (transposed)
    float4* sWs   = sWl + 1024;               // 8*192  f4 = 24 KB (transposed)
    float*  sh    = (float*)(sWs + 1536);     // 64*32  f  =  8 KB
    float*  satts = sh + 2048;                // 192
    float*  sattd = satts + 192;              // 192

    int tid = threadIdx.x;
    int base = blockIdx.x * 64;
    const float4* W4l = (const float4*)W_lin;   // [o][kc] 32x32
    for (int idx = tid; idx < 1024; idx += 256) {
        int o = idx >> 5, kc = idx & 31;
        sWl[kc * 32 + o] = W4l[idx];
    }
    const float4* W4s = (const float4*)Wsrc;    // [c][kc] 192x8
    for (int idx = tid; idx < 1536; idx += 256) {
        int c = idx >> 3, kc = idx & 7;
        sWs[kc * 192 + c] = W4s[idx];
    }
    if (tid < 192) { satts[tid] = att_s[tid]; sattd[tid] = att_d[tid]; }
    const float4* x4 = (const float4*)x;
    for (int idx = tid; idx < 2048; idx += 256)
        sx[idx] = x4[(size_t)base * 32 + idx];
    __syncthreads();

    int lane = tid & 31, w = tid >> 5;
    // ---- stage 1: h ----
    {
        float acc[8];
#pragma unroll
        for (int n = 0; n < 8; n++) acc[n] = 0.f;
#pragma unroll 8
        for (int kc = 0; kc < 32; kc++) {
            float4 wv = sWl[kc * 32 + lane];
#pragma unroll
            for (int n = 0; n < 8; n++) {
                float4 xv = sx[(8 * w + n) * 32 + kc];
                acc[n] += xv.x * wv.x + xv.y * wv.y + xv.z * wv.z + xv.w * wv.w;
            }
        }
        float bb = b_lin[lane];
#pragma unroll
        for (int n = 0; n < 8; n++) {
            float v = acc[n] + bb;
            sh[(8 * w + n) * 32 + lane] = v > 0.f ? v : __expf(v) - 1.f;
        }
    }
    __syncthreads();

    // ---- stage 2: xp + attention logits ----
    const float4* sh4 = (const float4*)sh;     // [node][kc] 64x8
    float acc[8][6];
#pragma unroll
    for (int n = 0; n < 8; n++)
#pragma unroll
        for (int j = 0; j < 6; j++) acc[n][j] = 0.f;
#pragma unroll
    for (int kc = 0; kc < 8; kc++) {
        float4 wv[6];
#pragma unroll
        for (int j = 0; j < 6; j++) wv[j] = sWs[kc * 192 + lane + 32 * j];
#pragma unroll
        for (int n = 0; n < 8; n++) {
            float4 hv = sh4[(8 * w + n) * 8 + kc];
#pragma unroll
            for (int j = 0; j < 6; j++)
                acc[n][j] += hv.x * wv[j].x + hv.y * wv[j].y
                           + hv.z * wv[j].z + hv.w * wv[j].w;
        }
    }
#pragma unroll
    for (int n = 0; n < 8; n++) {
        int node = base + 8 * w + n;
        float ps[3] = {0.f, 0.f, 0.f}, pd[3] = {0.f, 0.f, 0.f};
#pragma unroll
        for (int j = 0; j < 6; j++) {
            int c = lane + 32 * j;
            g_xp[(size_t)node * HCc + c] = acc[n][j];
            ps[j >> 1] += acc[n][j] * satts[c];
            pd[j >> 1] += acc[n][j] * sattd[c];
        }
#pragma unroll
        for (int h = 0; h < 3; h++) {
            float a = ps[h], d = pd[h];
#pragma unroll
            for (int o = 16; o > 0; o >>= 1) {
                a += __shfl_xor_sync(FULLM, a, o);
                d += __shfl_xor_sync(FULLM, d, o);
            }
            if (lane == 0) {
                ((float*)&g_asrc4[node])[h] = a;
                ((float*)&g_adst4[node])[h] = d;
            }
        }
    }
}

// ---------------- per-edge: count + bucket{src,e0,e1} ----------------------
__global__ void k_edge(const int* __restrict__ ei, const float* __restrict__ ea) {
    int e = blockIdx.x * blockDim.x + threadIdx.x;
    if (e >= Ee) return;
    int s = ei[e], d = ei[Ee + e];
    float2 a = ((const float2*)ea)[e];
    int p = atomicAdd(&g_cnt[d], 1);
    if (p < CAP)
        g_bucket[d * CAP + p] = make_float4(__int_as_float(s), a.x, a.y, 0.f);
}

// ---------------- GAT aggregation: head-per-warp, 2 nodes/block -------------
// block 192 = 6 warps.  warp w: node = blockIdx*2 + w/3, head = w%3.
// channel map within head: c = 64*head + 2*lane (float2 per lane).
__global__ __launch_bounds__(192) void k_agg(const float* __restrict__ b_gat,
                                             const float* __restrict__ Wg) {
    __shared__ float sxw[6];
    int tid = threadIdx.x, lane = tid & 31, wid = tid >> 5;   // 0..5
    int local = (wid >= 3) ? 1 : 0;
    int head = wid - 3 * local;
    int i = blockIdx.x * 2 + local;
    int deg = min(g_cnt[i], CAP);
    float A0 = g_A[2 * head], A1 = g_A[2 * head + 1];

    float4 fA = make_float4(0.f, 0.f, 0.f, 0.f), fB = fA;
    if (lane < deg)      fA = g_bucket[i * CAP + lane];
    if (32 + lane < deg) fB = g_bucket[i * CAP + 32 + lane];

    // loop-attr means
    float es0 = fA.y + fB.y, es1 = fA.z + fB.z;
#pragma unroll
    for (int o = 16; o > 0; o >>= 1) {
        es0 += __shfl_xor_sync(FULLM, es0, o);
        es1 += __shfl_xor_sync(FULLM, es1, o);
    }
    float inv = 1.f / fmaxf((float)deg, 1.f);
    float la0 = es0 * inv, la1 = es1 * inv;

    float adh = ((const float*)(g_adst4 + i))[head];
    float ash = ((const float*)(g_asrc4 + i))[head];
    float lvt = ash + adh + la0 * A0 + la1 * A1;
    float lv = lvt > 0.f ? lvt : 0.2f * lvt;

    // per-lane edge logits (this head only)
    int sA = __float_as_int(fA.x), sB = __float_as_int(fB.x);
    float aA = -1e30f, aB = -1e30f;
    if (lane < deg) {
        float sv = ((const float*)(g_asrc4 + sA))[head];
        float a = sv + adh + fA.y * A0 + fA.z * A1;
        aA = a > 0.f ? a : 0.2f * a;
    }
    if (32 + lane < deg) {
        float sv = ((const float*)(g_asrc4 + sB))[head];
        float a = sv + adh + fB.y * A0 + fB.z * A1;
        aB = a > 0.f ? a : 0.2f * a;
    }
    // softmax
    float m = fmaxf(lv, fmaxf(aA, aB));
#pragma unroll
    for (int o = 16; o > 0; o >>= 1)
        m = fmaxf(m, __shfl_xor_sync(FULLM, m, o));
    float wA = __expf(aA - m), wB = __expf(aB - m), sw = __expf(lv - m);
    float den = wA + wB;
#pragma unroll
    for (int o = 16; o > 0; o >>= 1)
        den += __shfl_xor_sync(FULLM, den, o);
    float r = 1.f / (sw + den + 1e-16f);

    // self contribution (c = 64*head + 2*lane)
    const float2* xp2 = (const float2*)g_xp;
    size_t hoff = (size_t)head * 32 + lane;
    float2 v = xp2[(size_t)i * 96 + hoff];
    float ax = sw * v.x, ay = sw * v.y;

    // edge loop: 2 SHFL + 1 LDG.64 + 2 FFMA per edge, unroll x2
    int dmain = min(deg, 32);
    int j = 0;
    for (; j + 1 < dmain; j += 2) {
        int   p0 = __shfl_sync(FULLM, sA, j);
        int   p1 = __shfl_sync(FULLM, sA, j + 1);
        float u0 = __shfl_sync(FULLM, wA, j);
        float u1 = __shfl_sync(FULLM, wA, j + 1);
        float2 v0 = xp2[(size_t)p0 * 96 + hoff];
        float2 v1 = xp2[(size_t)p1 * 96 + hoff];
        ax += u0 * v0.x + u1 * v1.x;
        ay += u0 * v0.y + u1 * v1.y;
    }
    if (j < dmain) {
        int   p0 = __shfl_sync(FULLM, sA, j);
        float u0 = __shfl_sync(FULLM, wA, j);
        float2 v0 = xp2[(size_t)p0 * 96 + hoff];
        ax += u0 * v0.x;
        ay += u0 * v0.y;
    }
    for (int t = 32; t < deg; t++) {          // rare tail (deg > 32)
        int   p0 = __shfl_sync(FULLM, sB, t - 32);
        float u0 = __shfl_sync(FULLM, wB, t - 32);
        float2 v0 = xp2[(size_t)p0 * 96 + hoff];
        ax += u0 * v0.x;
        ay += u0 * v0.y;
    }

    // epilogue: bias + relu + store + partial Wg dot
    float2 bv = ((const float2*)b_gat)[hoff];
    float2 wv = ((const float2*)Wg)[hoff];
    float2 o2;
    o2.x = fmaxf(ax * r + bv.x, 0.f);
    o2.y = fmaxf(ay * r + bv.y, 0.f);
    ((float2*)g_x1)[(size_t)i * 96 + hoff] = o2;
    float xw = o2.x * wv.x + o2.y * wv.y;
#pragma unroll
    for (int o = 16; o > 0; o >>= 1)
        xw += __shfl_xor_sync(FULLM, xw, o);
    if (lane == 0) sxw[wid] = xw;
    __syncthreads();
    if (lane == 0 && head == 0) {
        float t = sxw[3 * local] + sxw[3 * local + 1] + sxw[3 * local + 2];
        float dinv = rsqrtf((float)deg + 1.f);
        g_dinv[i] = dinv;
        g_q[i] = dinv * t;
    }
}

// ---------------- GCN score: warp-per-node gather of q ----------------------
__global__ void k_gcn(const float* __restrict__ b_gcn) {
    int warp = (blockIdx.x * blockDim.x + threadIdx.x) >> 5;
    int lane = threadIdx.x & 31;
    if (warp >= Nn) return;
    int i = warp;
    int deg = min(g_cnt[i], CAP);
    float sum = 0.f;
    if (lane < deg)
        sum += g_q[__float_as_int(g_bucket[i * CAP + lane].x)];
    if (lane + 32 < deg)
        sum += g_q[__float_as_int(g_bucket[i * CAP + lane + 32].x)];
#pragma unroll
    for (int o = 16; o > 0; o >>= 1)
        sum += __shfl_xor_sync(FULLM, sum, o);
    if (lane == 0)
        g_score[i] = g_dinv[i] * (sum + g_q[i]) + b_gcn[0];
}

// ---------------- SAGPool top-k mask + gmp/gap pooling ----------------------
__global__ void k_pool() {
    __shared__ float ss[512], sw[512];
    __shared__ unsigned char smk[512];
    __shared__ float pmax[2 * 192], psum[2 * 192];
    int b = blockIdx.x, t = threadIdx.x;
    float s = g_score[b * 512 + t];
    ss[t] = s;
    __syncthreads();
    int cnt = 0;
#pragma unroll 8
    for (int j = 0; j < 512; j++) {
        float sj = ss[j];
        cnt += (sj > s) || (sj == s && j < t);
    }
    smk[t] = (cnt < KEEP) ? 1 : 0;
    sw[t] = tanhf(s);
    __syncthreads();
    if (t < 384) {
        int strip = t / 192, c = t % 192;
        const float* xb = g_x1 + ((size_t)b * 512 + strip * 256) * HCc + c;
        float mx = -INFINITY, sum = 0.f;
#pragma unroll 4
        for (int n = 0; n < 256; n++) {
            int node = strip * 256 + n;
            if (smk[node]) {
                float v = xb[(size_t)n * HCc] * sw[node];
                mx = fmaxf(mx, v);
                sum += v;
            }
        }
        pmax[t] = mx;
        psum[t] = sum;
    }
    __syncthreads();
    if (t < 192) {
        g_r[b * 384 + t] = fmaxf(pmax[t], pmax[192 + t]);
        g_r[b * 384 + 192 + t] = (psum[t] + psum[192 + t]) * (1.f / (float)KEEP);
    }
}

// ---------------- classifier MLP + log_softmax ------------------------------
__global__ void k_mlp(const float* __restrict__ W1, const float* __restrict__ b1,
                      const float* __restrict__ W2, const float* __restrict__ b2,
                      const float* __restrict__ W3, const float* __restrict__ b3,
                      float* __restrict__ out) {
    __shared__ float sr[384];
    __shared__ float s1[64];
    __shared__ float s2[32];
    __shared__ float sl[10];
    int b = blockIdx.x, t = threadIdx.x;   // 64 threads
    for (int i = t; i < 384; i += 64) sr[i] = g_r[b * 384 + i];
    __syncthreads();
    {
        float a = 0.f;
        for (int k = 0; k < 384; k++) a += sr[k] * W1[t * 384 + k];
        a += b1[t];
        s1[t] = a > 0.f ? a : 0.f;
    }
    __syncthreads();
    if (t < 32) {
        float a = 0.f;
        for (int k = 0; k < 64; k++) a += s1[k] * W2[t * 64 + k];
        a += b2[t];
        s2[t] = a > 0.f ? a : 0.f;
    }
    __syncthreads();
    if (t < 10) {
        float a = 0.f;
        for (int k = 0; k < 32; k++) a += s2[k] * W3[t * 32 + k];
        sl[t] = a + b3[t];
    }
    __syncthreads();
    if (t == 0) {
        float mx = sl[0];
        for (int c = 1; c < 10; c++) mx = fmaxf(mx, sl[c]);
        float se = 0.f;
        for (int c = 0; c < 10; c++) se += __expf(sl[c] - mx);
        float lse = mx + __logf(se);
        for (int c = 0; c < 10; c++) out[b * 10 + c] = sl[c] - lse;
    }
}

// ---------------- launch ----------------------------------------------------
extern "C" void kernel_launch(void* const* d_in, const int* in_sizes, int n_in,
                              void* d_out, int out_size) {
    const float* x        = (const float*)d_in[0];
    const int*   ei       = (const int*)d_in[1];
    const float* ea       = (const float*)d_in[2];
    // d_in[3] = batch (unused; graphs are contiguous NPG blocks)
    const float* W_lin    = (const float*)d_in[4];
    const float* b_lin    = (const float*)d_in[5];
    const float* W_src    = (const float*)d_in[6];
    const float* att_src  = (const float*)d_in[7];
    const float* att_dst  = (const float*)d_in[8];
    const float* W_edge   = (const float*)d_in[9];
    const float* att_edge = (const float*)d_in[10];
    const float* b_gat    = (const float*)d_in[11];
    const float* W_gcn    = (const float*)d_in[12];
    const float* b_gcn    = (const float*)d_in[13];
    const float* W1       = (const float*)d_in[14];
    const float* b1       = (const float*)d_in[15];
    const float* W2       = (const float*)d_in[16];
    const float* b2       = (const float*)d_in[17];
    const float* W3       = (const float*)d_in[18];
    const float* b3       = (const float*)d_in[19];
    float* out = (float*)d_out;

    static int once = 0;
    static cudaStream_t s2;
    static cudaEvent_t evFork, evJoin;
    const int FEAT_SMEM = 84 * 1024;
    if (!once) {
        cudaFuncSetAttribute(k_feat, cudaFuncAttributeMaxDynamicSharedMemorySize,
                             FEAT_SMEM);
        cudaStreamCreateWithFlags(&s2, cudaStreamNonBlocking);
        cudaEventCreateWithFlags(&evFork, cudaEventDisableTiming);
        cudaEventCreateWithFlags(&evJoin, cudaEventDisableTiming);
        once = 1;
    }

    // fork: edge-bucket build runs concurrently with the feature GEMMs
    cudaEventRecord(evFork, 0);
    cudaStreamWaitEvent(s2, evFork, 0);
    k_init<<<Nn / 256, 256, 0, s2>>>(W_edge, att_edge);
    k_edge<<<Ee / 256, 256, 0, s2>>>(ei, ea);
    cudaEventRecord(evJoin, s2);

    k_feat<<<Nn / 64, 256, FEAT_SMEM>>>(x, W_lin, b_lin, W_src, att_src, att_dst);

    // join before aggregation
    cudaStreamWaitEvent(0, evJoin, 0);
    k_agg<<<Nn / 2, 192>>>(b_gat, W_gcn);
    k_gcn<<<Nn / 8, 256>>>(b_gcn);
    k_pool<<<Bb, 512>>>();
    k_mlp<<<Bb, 64>>>(W1, b1, W2, b2, W3, b3, out);
}